// round 15
// baseline (speedup 1.0000x reference)
#include <cuda_runtime.h>
#include <math.h>

// ---------------------------------------------------------------------------
// RowWiseGatedAttention — tf32 mma.sync; R11 attention + 128x256-tile GEMMs.
// B=1, c_m=256, s=128, i=256, H=8, c_head=32, c_z=128.
// ---------------------------------------------------------------------------

#define CM     256
#define S_DIM  128
#define I_DIM  256
#define NCOL   32768            // S_DIM * I_DIM
#define CZ     128
#define IJ     65536            // I_DIM * I_DIM
#define NH     8
#define NTOT   8388608          // CM*NCOL == CZ*IJ
#define LN_EPS 1e-5f

// ---------------- scratch (static device globals; no allocation) -----------
__device__ unsigned g_x[(size_t)CM * NCOL];        // LN1(msa), tf32 bits [c][s*i]
__device__ float    g_qkvg[(size_t)4 * CM * NCOL]; // q,k,v (tf32-rounded), g (fp32)
__device__ float    g_bias[(size_t)NH * IJ];       // pair bias [h][i*j]
__device__ float    g_o[(size_t)CM * NCOL];        // gated attn out (tf32-rounded)
__device__ unsigned g_wstack[1024 * 256];          // Wq,Wk,Wv,Wg tf32 bits
__device__ unsigned g_wrep[256 * 256];             // Wrep tf32 bits
__device__ float2   g_part[2][1024];

// ---------------- tf32 / mma / ldmatrix helpers -----------------------------
__device__ __forceinline__ unsigned f2tf(float x) {
    unsigned r; asm("cvt.rna.tf32.f32 %0, %1;" : "=r"(r) : "f"(x)); return r;
}
__device__ __forceinline__ void mma_tf32(float* c, unsigned a0, unsigned a1,
                                         unsigned a2, unsigned a3,
                                         unsigned b0, unsigned b1) {
    asm volatile(
        "mma.sync.aligned.m16n8k8.row.col.f32.tf32.tf32.f32 "
        "{%0,%1,%2,%3}, {%4,%5,%6,%7}, {%8,%9}, {%0,%1,%2,%3};"
        : "+f"(c[0]), "+f"(c[1]), "+f"(c[2]), "+f"(c[3])
        : "r"(a0), "r"(a1), "r"(a2), "r"(a3), "r"(b0), "r"(b1));
}
__device__ __forceinline__ void cpa16(unsigned saddr, const void* g) {
    asm volatile("cp.async.ca.shared.global [%0], [%1], 16;" :: "r"(saddr), "l"(g));
}
__device__ __forceinline__ void ldsm_x4(unsigned& r0, unsigned& r1,
                                        unsigned& r2, unsigned& r3, unsigned addr) {
    asm volatile("ldmatrix.sync.aligned.m8n8.x4.shared.b16 {%0,%1,%2,%3}, [%4];"
                 : "=r"(r0), "=r"(r1), "=r"(r2), "=r"(r3) : "r"(addr));
}
// A-fragment (m16 x k8) address for this lane: base over [row][stride] tf32 array
__device__ __forceinline__ unsigned lds_addr_a(unsigned base, int row0, int col, int stride) {
    int lane = threadIdx.x & 31;
    int g = lane >> 3, lr = lane & 7;
    int row = row0 + lr + ((g & 1) << 3);
    int c = col + ((g >> 1) << 2);
    return base + (unsigned)((row * stride + c) << 2);
}
// B-fragment (n8 x k16) address: array is [n][k] (row-major over k)
__device__ __forceinline__ unsigned lds_addr_b(unsigned base, int n0, int k0, int stride) {
    int lane = threadIdx.x & 31;
    int g = lane >> 3, lr = lane & 7;
    return base + (unsigned)(((n0 + lr) * stride + k0 + (g << 2)) << 2);
}

// ---------------- merged pre-pass: weight cvt + both partial reductions -----
__global__ void __launch_bounds__(256) k_pre(const float* __restrict__ msa,
                                             const float* __restrict__ pair,
                                             const float* __restrict__ Wq,
                                             const float* __restrict__ Wk,
                                             const float* __restrict__ Wv,
                                             const float* __restrict__ Wg,
                                             const float* __restrict__ Wrep) {
    int bid = blockIdx.x;
    if (bid >= 512) {                // weight conversion blocks
        int t = (bid - 512) * 256 + threadIdx.x;     // 0..327679
        if (t < 262144) {
            int sel = t >> 16, off = t & 65535;
            const float* W = (sel == 0) ? Wq : (sel == 1) ? Wk : (sel == 2) ? Wv : Wg;
            g_wstack[t] = f2tf(W[off]);
        } else {
            int off = t - 262144;
            g_wrep[off] = f2tf(Wrep[off]);
        }
        return;
    }
    int which = bid >> 8;
    const float4* s4 = (const float4*)(which ? pair : msa);
    int t = (bid & 255) * 256 + threadIdx.x;         // 0..65535
    float s = 0.f, ss = 0.f;
#pragma unroll 8
    for (int k = 0; k < 32; k++) {
        float4 v = s4[t + k * 65536];
        s  += v.x + v.y + v.z + v.w;
        ss += v.x * v.x + v.y * v.y + v.z * v.z + v.w * v.w;
    }
    __shared__ float sh[256], sh2[256];
    int tid = threadIdx.x;
    sh[tid] = s; sh2[tid] = ss;
    __syncthreads();
    for (int off = 128; off; off >>= 1) {
        if (tid < off) { sh[tid] += sh[tid + off]; sh2[tid] += sh2[tid + off]; }
        __syncthreads();
    }
    if (tid == 0) g_part[which][bid & 255] = make_float2(sh[0], sh2[0]);
}

// ---------------- per-block stats reduce (deterministic, same every block) --
__device__ __forceinline__ void block_stats(int which, float& mu_out, float& rs_out) {
    int tid = threadIdx.x, lane = tid & 31, warp = tid >> 5;
    float2 p = g_part[which][tid];
    float v0 = p.x, v1 = p.y;
#pragma unroll
    for (int off = 16; off; off >>= 1) {
        v0 += __shfl_xor_sync(0xffffffffu, v0, off);
        v1 += __shfl_xor_sync(0xffffffffu, v1, off);
    }
    __shared__ float w0[8], w1[8];
    __shared__ float s_mu, s_rs;
    if (lane == 0) { w0[warp] = v0; w1[warp] = v1; }
    __syncthreads();
    if (tid == 0) {
        float a = 0.f, b = 0.f;
#pragma unroll
        for (int k = 0; k < 8; k++) { a += w0[k]; b += w1[k]; }
        const float invN = 1.f / (float)NTOT;
        float mu = a * invN;
        float var = b * invN - mu * mu;
        s_mu = mu; s_rs = rsqrtf(var + LN_EPS);
    }
    __syncthreads();
    mu_out = s_mu; rs_out = s_rs;
}

// ---------------- merged LN1 apply + pair-bias GEMV (stats fused) -----------
__global__ void __launch_bounds__(256) k_ln1bias(const float* __restrict__ msa,
                                                 const float* __restrict__ w,
                                                 const float* __restrict__ b,
                                                 const float* __restrict__ pair,
                                                 const float* __restrict__ ln2w,
                                                 const float* __restrict__ ln2b,
                                                 const float* __restrict__ Wb) {
    int bid = blockIdx.x;
    if (bid < 8192) {                 // LN1 -> g_x tf32
        float mu, rs;
        block_stats(0, mu, rs);
        int t = bid * 256 + threadIdx.x;
        float4 m = ((const float4*)msa)[t];
        float4 ww = ((const float4*)w)[t];
        float4 bb = ((const float4*)b)[t];
        uint4 o;
        o.x = f2tf((m.x - mu) * rs * ww.x + bb.x);
        o.y = f2tf((m.y - mu) * rs * ww.y + bb.y);
        o.z = f2tf((m.z - mu) * rs * ww.z + bb.z);
        o.w = f2tf((m.w - mu) * rs * ww.w + bb.w);
        ((uint4*)g_x)[t] = o;
        return;
    }
    // pair bias blocks: 8192..8447
    float mu, rs;
    block_stats(1, mu, rs);
    __shared__ float wb_s[NH * CZ];
    int tid = threadIdx.x;
    for (int e = tid; e < NH * CZ; e += 256) wb_s[e] = Wb[e];
    __syncthreads();
    int col = (bid - 8192) * 256 + tid;
    float acc[NH];
#pragma unroll
    for (int o = 0; o < NH; o++) acc[o] = 0.f;
#pragma unroll 4
    for (int c = 0; c < CZ; c++) {
        size_t idx = (size_t)c * IJ + col;
        float z = (pair[idx] - mu) * rs * ln2w[idx] + ln2b[idx];
#pragma unroll
        for (int o = 0; o < NH; o++) acc[o] += wb_s[o * CZ + c] * z;
    }
#pragma unroll
    for (int o = 0; o < NH; o++) g_bias[(size_t)o * IJ + col] = acc[o];
}

// ---------------- tf32 GEMM: [M x 256] @ [256 x 32768], 128x256 CTA tile ----
// 512 threads (16 warps, 64x32 warp tiles). Dynamic smem 53KB (opt-in).
#define GEMM_SMEM ((2 * 128 * 20 + 2 * 16 * 264) * 4)

template<int MODE>
__global__ void __launch_bounds__(512) k_gemm(const float* __restrict__ bias,
                                              float* __restrict__ Cout) {
    extern __shared__ unsigned gsm[];
    // layout: As[2][128][20] | Bs[2][16][264]
    unsigned (*As)[128][20]  = (unsigned(*)[128][20])gsm;
    unsigned (*Bs)[16][264]  = (unsigned(*)[16][264])(gsm + 2 * 128 * 20);

    const unsigned* A = MODE ? g_wstack : g_wrep;
    const unsigned* B = MODE ? g_x : (const unsigned*)g_o;
    float* C = MODE ? g_qkvg : Cout;

    const int tid = threadIdx.x;
    const int lane = tid & 31, warp = tid >> 5;
    const int wm = (warp & 1) * 64, wn = (warp >> 1) * 32;   // 2 x 8 warp grid
    const int bm = blockIdx.y * 128, bn = blockIdx.x * 256;

    float acc[4][4][4];
#pragma unroll
    for (int i = 0; i < 4; i++)
#pragma unroll
        for (int j = 0; j < 4; j++)
#pragma unroll
            for (int k = 0; k < 4; k++) acc[i][j][k] = 0.f;

    unsigned sAb = (unsigned)__cvta_generic_to_shared(&As[0][0][0]);
    unsigned sBb = (unsigned)__cvta_generic_to_shared(&Bs[0][0][0]);

    auto load_tiles = [&](int buf, int k0) {
        {   // A: 128 rows x 16 k -> 512 cpa (1 per thread)
            int row = tid >> 2, c4 = (tid & 3) << 2;
            cpa16(sAb + (((buf * 128 + row) * 20 + c4) << 2),
                  A + (size_t)(bm + row) * 256 + k0 + c4);
        }
#pragma unroll
        for (int i = 0; i < 2; i++) {   // B: 16 k x 256 n -> 1024 cpa
            int idx = tid + i * 512;
            int kk = idx >> 6, c4 = (idx & 63) << 2;
            cpa16(sBb + (((buf * 16 + kk) * 264 + c4) << 2),
                  B + (size_t)(k0 + kk) * NCOL + bn + c4);
        }
        asm volatile("cp.async.commit_group;" ::: "memory");
    };

    load_tiles(0, 0);
    int buf = 0;
    const int r = lane >> 2, cq = lane & 3;
    for (int it = 0; it < 16; it++) {
        asm volatile("cp.async.wait_group 0;" ::: "memory");
        __syncthreads();
        if (it < 15) load_tiles(buf ^ 1, (it + 1) * 16);
        unsigned abase = sAb + (unsigned)((buf * 128 * 20) << 2);
        unsigned a[4][2][4];
#pragma unroll
        for (int mi = 0; mi < 4; mi++) {
            ldsm_x4(a[mi][0][0], a[mi][0][1], a[mi][0][2], a[mi][0][3],
                    lds_addr_a(abase, wm + mi * 16, 0, 20));
            ldsm_x4(a[mi][1][0], a[mi][1][1], a[mi][1][2], a[mi][1][3],
                    lds_addr_a(abase, wm + mi * 16, 8, 20));
        }
#pragma unroll
        for (int ks = 0; ks < 2; ks++) {
            int k8 = ks * 8;
            unsigned b[4][2];
#pragma unroll
            for (int ni = 0; ni < 4; ni++) {
                int cb = wn + ni * 8 + r;
                b[ni][0] = Bs[buf][k8 + cq][cb];
                b[ni][1] = Bs[buf][k8 + 4 + cq][cb];
            }
#pragma unroll
            for (int mi = 0; mi < 4; mi++)
#pragma unroll
                for (int ni = 0; ni < 4; ni++)
                    mma_tf32(acc[mi][ni], a[mi][ks][0], a[mi][ks][1],
                             a[mi][ks][2], a[mi][ks][3], b[ni][0], b[ni][1]);
        }
        buf ^= 1;
    }

#pragma unroll
    for (int mi = 0; mi < 4; mi++) {
        int row = bm + wm + mi * 16 + r;
#pragma unroll
        for (int ni = 0; ni < 4; ni++) {
            int col = bn + wn + ni * 8 + 2 * cq;
            float v0 = acc[mi][ni][0], v1 = acc[mi][ni][1];
            float v2 = acc[mi][ni][2], v3 = acc[mi][ni][3];
            if (MODE == 1) {
                if (bm >= 768) {
                    float b0 = bias[row - 768], b8 = bias[row - 768 + 8];
                    v0 = 1.f / (1.f + __expf(-(v0 + b0)));
                    v1 = 1.f / (1.f + __expf(-(v1 + b0)));
                    v2 = 1.f / (1.f + __expf(-(v2 + b8)));
                    v3 = 1.f / (1.f + __expf(-(v3 + b8)));
                } else {
                    v0 = __uint_as_float(f2tf(v0));
                    v1 = __uint_as_float(f2tf(v1));
                    v2 = __uint_as_float(f2tf(v2));
                    v3 = __uint_as_float(f2tf(v3));
                }
            } else {
                float b0 = bias[row], b8 = bias[row + 8];
                v0 += b0; v1 += b0; v2 += b8; v3 += b8;
            }
            *(float2*)&C[(size_t)row * NCOL + col]       = make_float2(v0, v1);
            *(float2*)&C[(size_t)(row + 8) * NCOL + col] = make_float2(v2, v3);
        }
    }
}

// ---------------- flash attention (R11 winner, byte-identical math) ---------
// block = (i-64, s, h), 128 threads (4 warps x 16 rows), smem 44KB static.
#define QA 36   // qs [i][c] stride (conflict-free ldsm A)
#define KA 72   // ks [c][j] stride (conflict-free scalar B-LDS)
#define VA 68   // vs [c][j] stride (conflict-free ldsm B)

__global__ void __launch_bounds__(128, 4) k_attn() {
    __shared__ unsigned qs[64 * QA];
    __shared__ unsigned ks[2][32 * KA];
    __shared__ unsigned vs[2][32 * VA];

    int ib = blockIdx.x, s = blockIdx.y, h = blockIdx.z;
    int ibase = ib * 64;
    int tid = threadIdx.x, lane = tid & 31, warp = tid >> 5;
    size_t colb = (size_t)s * 256;
    const unsigned* qg = (const unsigned*)g_qkvg;
    const uint4* qg4 = (const uint4*)g_qkvg;

    unsigned qs_sh = (unsigned)__cvta_generic_to_shared(qs);
    unsigned ks_sh = (unsigned)__cvta_generic_to_shared(&ks[0][0]);
    unsigned vs_sh = (unsigned)__cvta_generic_to_shared(&vs[0][0]);

    // ---- cp.async stage K/V chunk 0 ([c][j], contiguous 16B) ----
#pragma unroll
    for (int it = 0; it < 4; it++) {
        int idx = tid + it * 128;
        int c = idx >> 4, j4 = (idx & 15) << 2;
        cpa16(ks_sh + (unsigned)((c * KA + j4) << 2),
              qg + ((size_t)(256 + h * 32 + c)) * NCOL + colb + j4);
        cpa16(vs_sh + (unsigned)((c * VA + j4) << 2),
              qg + ((size_t)(512 + h * 32 + c)) * NCOL + colb + j4);
    }
    asm volatile("cp.async.commit_group;" ::: "memory");

    // ---- stage Q [64 i][32 c] transposed (once) ----
#pragma unroll
    for (int it = 0; it < 4; it++) {
        int idx = tid + it * 128;
        int c = idx >> 4, i4 = idx & 15;
        uint4 v = qg4[(((size_t)(h * 32 + c)) * NCOL + colb + ibase + i4 * 4) >> 2];
        qs[(i4 * 4 + 0) * QA + c] = v.x;
        qs[(i4 * 4 + 1) * QA + c] = v.y;
        qs[(i4 * 4 + 2) * QA + c] = v.z;
        qs[(i4 * 4 + 3) * QA + c] = v.w;
    }
    asm volatile("cp.async.wait_group 0;" ::: "memory");
    __syncthreads();

    const float scale = 0.17677669529663687f;   // 1/sqrt(32)
    const float* biasp = g_bias + (size_t)h * IJ;
    const int r = lane >> 2, cq = lane & 3;
    const int wm = warp * 16;                  // warp's 16 i-rows

    // ---- preload Q a-fragments (persistent) ----
    unsigned qa[4][4];
    ldsm_x4(qa[0][0], qa[0][1], qa[0][2], qa[0][3], lds_addr_a(qs_sh, wm, 0, QA));
    ldsm_x4(qa[1][0], qa[1][1], qa[1][2], qa[1][3], lds_addr_a(qs_sh, wm, 8, QA));
    ldsm_x4(qa[2][0], qa[2][1], qa[2][2], qa[2][3], lds_addr_a(qs_sh, wm, 16, QA));
    ldsm_x4(qa[3][0], qa[3][1], qa[3][2], qa[3][3], lds_addr_a(qs_sh, wm, 24, QA));

    float acc2[4][4];                          // O accumulator: 16 rows x 32 c
#pragma unroll
    for (int ct = 0; ct < 4; ct++)
#pragma unroll
        for (int k = 0; k < 4; k++) acc2[ct][k] = 0.f;
    float m0 = -1e30f, m1 = -1e30f, l0 = 0.f, l1 = 0.f;

    for (int ch = 0; ch < 4; ch++) {
        int jb = ch * 64;
        int buf = ch & 1;
        const unsigned* kb = &ks[buf][0];
        unsigned vb_sh = vs_sh + (unsigned)((buf * 32 * VA) << 2);

        // ---- prefetch next K/V chunk into other buffer (cp.async) ----
        if (ch < 3) {
            unsigned ko = ks_sh + (unsigned)((((buf ^ 1) * 32 * KA)) << 2);
            unsigned vo = vs_sh + (unsigned)((((buf ^ 1) * 32 * VA)) << 2);
            int jb2 = jb + 64;
#pragma unroll
            for (int it = 0; it < 4; it++) {
                int idx = tid + it * 128;
                int c = idx >> 4, j4 = (idx & 15) << 2;
                cpa16(ko + (unsigned)((c * KA + j4) << 2),
                      qg + ((size_t)(256 + h * 32 + c)) * NCOL + colb + jb2 + j4);
                cpa16(vo + (unsigned)((c * VA + j4) << 2),
                      qg + ((size_t)(512 + h * 32 + c)) * NCOL + colb + jb2 + j4);
            }
            asm volatile("cp.async.commit_group;" ::: "memory");
        }

        // ---- hoisted bias loads (overlap with QK mma) ----
        float2 bb0[8], bb8[8];
        {
            const float* bp0 = biasp + (size_t)(ibase + wm + r) * 256 + jb;
            const float* bp8 = bp0 + 8 * 256;
#pragma unroll
            for (int ni = 0; ni < 8; ni++) {
                bb0[ni] = *(const float2*)(bp0 + ni * 8 + 2 * cq);
                bb8[ni] = *(const float2*)(bp8 + ni * 8 + 2 * cq);
            }
        }

        // ---- QK: M=16(i), N=64(j), K=32(c); B via conflict-free scalar LDS --
        float acc[8][4];
#pragma unroll
        for (int ni = 0; ni < 8; ni++)
#pragma unroll
            for (int k = 0; k < 4; k++) acc[ni][k] = 0.f;
#pragma unroll
        for (int kk = 0; kk < 4; kk++) {
#pragma unroll
            for (int ni = 0; ni < 8; ni++) {
                unsigned b0 = kb[(kk * 8 + cq) * KA + ni * 8 + r];
                unsigned b1 = kb[(kk * 8 + 4 + cq) * KA + ni * 8 + r];
                mma_tf32(acc[ni], qa[kk][0], qa[kk][1], qa[kk][2], qa[kk][3], b0, b1);
            }
        }

        // ---- scale + bias (registers) ----
#pragma unroll
        for (int ni = 0; ni < 8; ni++) {
            acc[ni][0] = acc[ni][0] * scale + bb0[ni].x;
            acc[ni][1] = acc[ni][1] * scale + bb0[ni].y;
            acc[ni][2] = acc[ni][2] * scale + bb8[ni].x;
            acc[ni][3] = acc[ni][3] * scale + bb8[ni].y;
        }

        // ---- register online softmax (quad shuffles only) ----
        {
            float rmax0 = -1e30f, rmax1 = -1e30f;
#pragma unroll
            for (int ni = 0; ni < 8; ni++) {
                rmax0 = fmaxf(rmax0, fmaxf(acc[ni][0], acc[ni][1]));
                rmax1 = fmaxf(rmax1, fmaxf(acc[ni][2], acc[ni][3]));
            }
#pragma unroll
            for (int off = 1; off < 4; off <<= 1) {
                rmax0 = fmaxf(rmax0, __shfl_xor_sync(0xffffffffu, rmax0, off));
                rmax1 = fmaxf(rmax1, __shfl_xor_sync(0xffffffffu, rmax1, off));
            }
            float mn0 = fmaxf(m0, rmax0), mn1 = fmaxf(m1, rmax1);
            float al0 = __expf(m0 - mn0), al1 = __expf(m1 - mn1);
            m0 = mn0; m1 = mn1;
            float sum0 = 0.f, sum1 = 0.f;
#pragma unroll
            for (int ni = 0; ni < 8; ni++) {
                acc[ni][0] = __expf(acc[ni][0] - mn0);
                acc[ni][1] = __expf(acc[ni][1] - mn0);
                acc[ni][2] = __expf(acc[ni][2] - mn1);
                acc[ni][3] = __expf(acc[ni][3] - mn1);
                sum0 += acc[ni][0] + acc[ni][1];
                sum1 += acc[ni][2] + acc[ni][3];
            }
#pragma unroll
            for (int off = 1; off < 4; off <<= 1) {
                sum0 += __shfl_xor_sync(0xffffffffu, sum0, off);
                sum1 += __shfl_xor_sync(0xffffffffu, sum1, off);
            }
            l0 = al0 * l0 + sum0;
            l1 = al1 * l1 + sum1;
#pragma unroll
            for (int ct = 0; ct < 4; ct++) {
                acc2[ct][0] *= al0; acc2[ct][1] *= al0;
                acc2[ct][2] *= al1; acc2[ct][3] *= al1;
            }
        }

        // ---- permute C-frag -> A-frag (tf32), probs never touch smem ----
        unsigned au[8][4];
        {
            int src0 = (lane & 28) | (cq >> 1);
            int src1 = src0 + 2;
            bool odd = cq & 1;
#pragma unroll
            for (int ni = 0; ni < 8; ni++) {
                float p00 = __shfl_sync(0xffffffffu, acc[ni][0], src0);
                float p01 = __shfl_sync(0xffffffffu, acc[ni][1], src0);
                float p10 = __shfl_sync(0xffffffffu, acc[ni][0], src1);
                float p11 = __shfl_sync(0xffffffffu, acc[ni][1], src1);
                float q00 = __shfl_sync(0xffffffffu, acc[ni][2], src0);
                float q01 = __shfl_sync(0xffffffffu, acc[ni][3], src0);
                float q10 = __shfl_sync(0xffffffffu, acc[ni][2], src1);
                float q11 = __shfl_sync(0xffffffffu, acc[ni][3], src1);
                au[ni][0] = f2tf(odd ? p01 : p00);   // (r,   cq)
                au[ni][1] = f2tf(odd ? q01 : q00);   // (r+8, cq)
                au[ni][2] = f2tf(odd ? p11 : p10);   // (r,   cq+4)
                au[ni][3] = f2tf(odd ? q11 : q10);   // (r+8, cq+4)
            }
        }

        // ---- AV: M=16(i), N=32(c), K=64(j); A from registers, B ldsm ----
#pragma unroll
        for (int k16i = 0; k16i < 4; k16i++) {
#pragma unroll
            for (int ct = 0; ct < 4; ct++) {
                unsigned b[4];
                ldsm_x4(b[0], b[1], b[2], b[3],
                        lds_addr_b(vb_sh, ct * 8, k16i * 16, VA));
                mma_tf32(acc2[ct], au[2 * k16i][0], au[2 * k16i][1],
                         au[2 * k16i][2], au[2 * k16i][3], b[0], b[1]);
                mma_tf32(acc2[ct], au[2 * k16i + 1][0], au[2 * k16i + 1][1],
                         au[2 * k16i + 1][2], au[2 * k16i + 1][3], b[2], b[3]);
            }
        }

        if (ch < 3) {
            asm volatile("cp.async.wait_group 0;" ::: "memory");
            __syncthreads();
        }
    }

    // ---- epilogue: normalize, stage [c][i] into vs[0], gate + store ----
    __syncthreads();
    float* stage = (float*)&vs[0][0];
    {
        float inv0 = 1.f / l0, inv8 = 1.f / l1;
#pragma unroll
        for (int ct = 0; ct < 4; ct++) {
            int c = ct * 8 + 2 * cq;
            stage[c * VA + wm + r]           = acc2[ct][0] * inv0;
            stage[(c + 1) * VA + wm + r]     = acc2[ct][1] * inv0;
            stage[c * VA + wm + r + 8]       = acc2[ct][2] * inv8;
            stage[(c + 1) * VA + wm + r + 8] = acc2[ct][3] * inv8;
        }
    }
    __syncthreads();
    for (int e = tid; e < 2048; e += 128) {
        int c2 = e >> 6, ii = e & 63;
        size_t col = colb + ibase + ii;
        float gv = g_qkvg[((size_t)(768 + h * 32 + c2)) * NCOL + col];
        g_o[((size_t)(c2 * NH + h)) * NCOL + col] =
            __uint_as_float(f2tf(stage[c2 * VA + ii] * gv));
    }
}

// ---------------------------------------------------------------------------
extern "C" void kernel_launch(void* const* d_in, const int* in_sizes, int n_in,
                              void* d_out, int out_size) {
    const float* msa  = (const float*)d_in[0];
    const float* pair = (const float*)d_in[1];
    const float* ln1w = (const float*)d_in[2];
    const float* ln1b = (const float*)d_in[3];
    const float* ln2w = (const float*)d_in[4];
    const float* ln2b = (const float*)d_in[5];
    const float* Wq   = (const float*)d_in[6];
    const float* Wk   = (const float*)d_in[7];
    const float* Wv   = (const float*)d_in[8];
    const float* Wb   = (const float*)d_in[9];
    const float* Wg   = (const float*)d_in[10];
    const float* bg   = (const float*)d_in[11];
    const float* Wrep = (const float*)d_in[12];
    const float* brep = (const float*)d_in[13];
    float* out = (float*)d_out;

    // Opt-in to >48KB dynamic smem for the GEMMs (set on pre-capture call).
    cudaFuncAttributes attr;
    cudaFuncGetAttributes(&attr, k_gemm<1>);
    if (attr.maxDynamicSharedSizeBytes < (int)GEMM_SMEM) {
        cudaFuncSetAttribute(k_gemm<1>, cudaFuncAttributeMaxDynamicSharedMemorySize, GEMM_SMEM);
    }
    cudaFuncGetAttributes(&attr, k_gemm<0>);
    if (attr.maxDynamicSharedSizeBytes < (int)GEMM_SMEM) {
        cudaFuncSetAttribute(k_gemm<0>, cudaFuncAttributeMaxDynamicSharedMemorySize, GEMM_SMEM);
    }

    k_pre<<<512 + 1280, 256>>>(msa, pair, Wq, Wk, Wv, Wg, Wrep);
    k_ln1bias<<<8192 + 256, 256>>>(msa, ln1w, ln1b, pair, ln2w, ln2b, Wb);
    k_gemm<1><<<dim3(128, 8), 512, GEMM_SMEM>>>(bg, nullptr);
    k_attn<<<dim3(4, S_DIM, NH), 128>>>();
    k_gemm<0><<<dim3(128, 2), 512, GEMM_SMEM>>>(brep, out);
}

// round 16
// speedup vs baseline: 1.0583x; 1.0583x over previous
#include <cuda_runtime.h>
#include <math.h>

// ---------------------------------------------------------------------------
// RowWiseGatedAttention — tf32 mma.sync; R10 attention + 3-stage-pipe GEMMs.
// B=1, c_m=256, s=128, i=256, H=8, c_head=32, c_z=128.
// ---------------------------------------------------------------------------

#define CM     256
#define S_DIM  128
#define I_DIM  256
#define NCOL   32768            // S_DIM * I_DIM
#define CZ     128
#define IJ     65536            // I_DIM * I_DIM
#define NH     8
#define NTOT   8388608          // CM*NCOL == CZ*IJ
#define LN_EPS 1e-5f

// ---------------- scratch (static device globals; no allocation) -----------
__device__ unsigned g_x[(size_t)CM * NCOL];        // LN1(msa), tf32 bits [c][s*i]
__device__ float    g_qkvg[(size_t)4 * CM * NCOL]; // q,k,v (tf32-rounded), g (fp32)
__device__ float    g_bias[(size_t)NH * IJ];       // pair bias [h][i*j]
__device__ float    g_o[(size_t)CM * NCOL];        // gated attn out (tf32-rounded)
__device__ unsigned g_wstack[1024 * 256];          // Wq,Wk,Wv,Wg tf32 bits
__device__ unsigned g_wrep[256 * 256];             // Wrep tf32 bits
__device__ float2   g_part[2][1024];

// ---------------- tf32 / mma / ldmatrix helpers -----------------------------
__device__ __forceinline__ unsigned f2tf(float x) {
    unsigned r; asm("cvt.rna.tf32.f32 %0, %1;" : "=r"(r) : "f"(x)); return r;
}
__device__ __forceinline__ void mma_tf32(float* c, unsigned a0, unsigned a1,
                                         unsigned a2, unsigned a3,
                                         unsigned b0, unsigned b1) {
    asm volatile(
        "mma.sync.aligned.m16n8k8.row.col.f32.tf32.tf32.f32 "
        "{%0,%1,%2,%3}, {%4,%5,%6,%7}, {%8,%9}, {%0,%1,%2,%3};"
        : "+f"(c[0]), "+f"(c[1]), "+f"(c[2]), "+f"(c[3])
        : "r"(a0), "r"(a1), "r"(a2), "r"(a3), "r"(b0), "r"(b1));
}
__device__ __forceinline__ void cpa16(unsigned saddr, const void* g) {
    asm volatile("cp.async.ca.shared.global [%0], [%1], 16;" :: "r"(saddr), "l"(g));
}
__device__ __forceinline__ void ldsm_x4(unsigned& r0, unsigned& r1,
                                        unsigned& r2, unsigned& r3, unsigned addr) {
    asm volatile("ldmatrix.sync.aligned.m8n8.x4.shared.b16 {%0,%1,%2,%3}, [%4];"
                 : "=r"(r0), "=r"(r1), "=r"(r2), "=r"(r3) : "r"(addr));
}
// A-fragment (m16 x k8) address for this lane: base over [row][stride] tf32 array
__device__ __forceinline__ unsigned lds_addr_a(unsigned base, int row0, int col, int stride) {
    int lane = threadIdx.x & 31;
    int g = lane >> 3, lr = lane & 7;
    int row = row0 + lr + ((g & 1) << 3);
    int c = col + ((g >> 1) << 2);
    return base + (unsigned)((row * stride + c) << 2);
}
// B-fragment (n8 x k16) address: array is [n][k] (row-major over k)
__device__ __forceinline__ unsigned lds_addr_b(unsigned base, int n0, int k0, int stride) {
    int lane = threadIdx.x & 31;
    int g = lane >> 3, lr = lane & 7;
    return base + (unsigned)(((n0 + lr) * stride + k0 + (g << 2)) << 2);
}

// ---------------- merged pre-pass: weight cvt + both partial reductions -----
__global__ void __launch_bounds__(256) k_pre(const float* __restrict__ msa,
                                             const float* __restrict__ pair,
                                             const float* __restrict__ Wq,
                                             const float* __restrict__ Wk,
                                             const float* __restrict__ Wv,
                                             const float* __restrict__ Wg,
                                             const float* __restrict__ Wrep) {
    int bid = blockIdx.x;
    if (bid >= 512) {                // weight conversion blocks
        int t = (bid - 512) * 256 + threadIdx.x;     // 0..327679
        if (t < 262144) {
            int sel = t >> 16, off = t & 65535;
            const float* W = (sel == 0) ? Wq : (sel == 1) ? Wk : (sel == 2) ? Wv : Wg;
            g_wstack[t] = f2tf(W[off]);
        } else {
            int off = t - 262144;
            g_wrep[off] = f2tf(Wrep[off]);
        }
        return;
    }
    int which = bid >> 8;
    const float4* s4 = (const float4*)(which ? pair : msa);
    int t = (bid & 255) * 256 + threadIdx.x;         // 0..65535
    float s = 0.f, ss = 0.f;
#pragma unroll 8
    for (int k = 0; k < 32; k++) {
        float4 v = s4[t + k * 65536];
        s  += v.x + v.y + v.z + v.w;
        ss += v.x * v.x + v.y * v.y + v.z * v.z + v.w * v.w;
    }
    __shared__ float sh[256], sh2[256];
    int tid = threadIdx.x;
    sh[tid] = s; sh2[tid] = ss;
    __syncthreads();
    for (int off = 128; off; off >>= 1) {
        if (tid < off) { sh[tid] += sh[tid + off]; sh2[tid] += sh2[tid + off]; }
        __syncthreads();
    }
    if (tid == 0) g_part[which][bid & 255] = make_float2(sh[0], sh2[0]);
}

// ---------------- per-block stats reduce (deterministic, same every block) --
__device__ __forceinline__ void block_stats(int which, float& mu_out, float& rs_out) {
    int tid = threadIdx.x, lane = tid & 31, warp = tid >> 5;
    float2 p = g_part[which][tid];
    float v0 = p.x, v1 = p.y;
#pragma unroll
    for (int off = 16; off; off >>= 1) {
        v0 += __shfl_xor_sync(0xffffffffu, v0, off);
        v1 += __shfl_xor_sync(0xffffffffu, v1, off);
    }
    __shared__ float w0[8], w1[8];
    __shared__ float s_mu, s_rs;
    if (lane == 0) { w0[warp] = v0; w1[warp] = v1; }
    __syncthreads();
    if (tid == 0) {
        float a = 0.f, b = 0.f;
#pragma unroll
        for (int k = 0; k < 8; k++) { a += w0[k]; b += w1[k]; }
        const float invN = 1.f / (float)NTOT;
        float mu = a * invN;
        float var = b * invN - mu * mu;
        s_mu = mu; s_rs = rsqrtf(var + LN_EPS);
    }
    __syncthreads();
    mu_out = s_mu; rs_out = s_rs;
}

// ---------------- merged LN1 apply + pair-bias GEMV (stats fused) -----------
__global__ void __launch_bounds__(256) k_ln1bias(const float* __restrict__ msa,
                                                 const float* __restrict__ w,
                                                 const float* __restrict__ b,
                                                 const float* __restrict__ pair,
                                                 const float* __restrict__ ln2w,
                                                 const float* __restrict__ ln2b,
                                                 const float* __restrict__ Wb) {
    int bid = blockIdx.x;
    if (bid < 8192) {                 // LN1 -> g_x tf32
        float mu, rs;
        block_stats(0, mu, rs);
        int t = bid * 256 + threadIdx.x;
        float4 m = ((const float4*)msa)[t];
        float4 ww = ((const float4*)w)[t];
        float4 bb = ((const float4*)b)[t];
        uint4 o;
        o.x = f2tf((m.x - mu) * rs * ww.x + bb.x);
        o.y = f2tf((m.y - mu) * rs * ww.y + bb.y);
        o.z = f2tf((m.z - mu) * rs * ww.z + bb.z);
        o.w = f2tf((m.w - mu) * rs * ww.w + bb.w);
        ((uint4*)g_x)[t] = o;
        return;
    }
    // pair bias blocks: 8192..8447
    float mu, rs;
    block_stats(1, mu, rs);
    __shared__ float wb_s[NH * CZ];
    int tid = threadIdx.x;
    for (int e = tid; e < NH * CZ; e += 256) wb_s[e] = Wb[e];
    __syncthreads();
    int col = (bid - 8192) * 256 + tid;
    float acc[NH];
#pragma unroll
    for (int o = 0; o < NH; o++) acc[o] = 0.f;
#pragma unroll 4
    for (int c = 0; c < CZ; c++) {
        size_t idx = (size_t)c * IJ + col;
        float z = (pair[idx] - mu) * rs * ln2w[idx] + ln2b[idx];
#pragma unroll
        for (int o = 0; o < NH; o++) acc[o] += wb_s[o * CZ + c] * z;
    }
#pragma unroll
    for (int o = 0; o < NH; o++) g_bias[(size_t)o * IJ + col] = acc[o];
}

// ---------------- tf32 GEMM: [M x 256] @ [256 x 32768], 128x128, 3-stage ----
// dyn smem 56.8KB: As[3][128][20] | Bs[3][16][136]
#define GEMM_SMEM ((3 * 128 * 20 + 3 * 16 * 136) * 4)

template<int MODE>
__global__ void __launch_bounds__(256) k_gemm(const float* __restrict__ bias,
                                              float* __restrict__ Cout) {
    extern __shared__ unsigned gsm[];
    unsigned (*As)[128][20] = (unsigned(*)[128][20])gsm;
    unsigned (*Bs)[16][136] = (unsigned(*)[16][136])(gsm + 3 * 128 * 20);

    const unsigned* A = MODE ? g_wstack : g_wrep;
    const unsigned* B = MODE ? g_x : (const unsigned*)g_o;
    float* C = MODE ? g_qkvg : Cout;

    const int tid = threadIdx.x;
    const int lane = tid & 31, warp = tid >> 5;
    const int wm = (warp & 1) * 64, wn = (warp >> 1) * 32;
    const int bm = blockIdx.y * 128, bn = blockIdx.x * 128;

    float acc[4][4][4];
#pragma unroll
    for (int i = 0; i < 4; i++)
#pragma unroll
        for (int j = 0; j < 4; j++)
#pragma unroll
            for (int k = 0; k < 4; k++) acc[i][j][k] = 0.f;

    unsigned sAb = (unsigned)__cvta_generic_to_shared(&As[0][0][0]);
    unsigned sBb = (unsigned)__cvta_generic_to_shared(&Bs[0][0][0]);

    auto load_tiles = [&](int buf, int k0) {
#pragma unroll
        for (int i = 0; i < 2; i++) {
            int idx = tid + i * 256;
            int row = idx >> 2, c4 = (idx & 3) << 2;
            cpa16(sAb + (((buf * 128 + row) * 20 + c4) << 2),
                  A + (size_t)(bm + row) * 256 + k0 + c4);
        }
#pragma unroll
        for (int i = 0; i < 2; i++) {
            int idx = tid + i * 256;
            int kk = idx >> 5, c4 = (idx & 31) << 2;
            cpa16(sBb + (((buf * 16 + kk) * 136 + c4) << 2),
                  B + (size_t)(k0 + kk) * NCOL + bn + c4);
        }
        asm volatile("cp.async.commit_group;" ::: "memory");
    };

    load_tiles(0, 0);
    load_tiles(1, 16);
    const int r = lane >> 2, cq = lane & 3;
    for (int it = 0; it < 16; it++) {
        int buf = it % 3;
        if (it < 15) asm volatile("cp.async.wait_group 1;" ::: "memory");
        else         asm volatile("cp.async.wait_group 0;" ::: "memory");
        __syncthreads();
        if (it < 14) load_tiles((it + 2) % 3, (it + 2) * 16);
        unsigned abase = sAb + (unsigned)((buf * 128 * 20) << 2);
        unsigned a[4][2][4];
#pragma unroll
        for (int mi = 0; mi < 4; mi++) {
            ldsm_x4(a[mi][0][0], a[mi][0][1], a[mi][0][2], a[mi][0][3],
                    lds_addr_a(abase, wm + mi * 16, 0, 20));
            ldsm_x4(a[mi][1][0], a[mi][1][1], a[mi][1][2], a[mi][1][3],
                    lds_addr_a(abase, wm + mi * 16, 8, 20));
        }
#pragma unroll
        for (int ks = 0; ks < 2; ks++) {
            int k8 = ks * 8;
            unsigned b[4][2];
#pragma unroll
            for (int ni = 0; ni < 4; ni++) {
                int cb = wn + ni * 8 + r;
                b[ni][0] = Bs[buf][k8 + cq][cb];
                b[ni][1] = Bs[buf][k8 + 4 + cq][cb];
            }
#pragma unroll
            for (int mi = 0; mi < 4; mi++)
#pragma unroll
                for (int ni = 0; ni < 4; ni++)
                    mma_tf32(acc[mi][ni], a[mi][ks][0], a[mi][ks][1],
                             a[mi][ks][2], a[mi][ks][3], b[ni][0], b[ni][1]);
        }
    }

#pragma unroll
    for (int mi = 0; mi < 4; mi++) {
        int row = bm + wm + mi * 16 + r;
#pragma unroll
        for (int ni = 0; ni < 4; ni++) {
            int col = bn + wn + ni * 8 + 2 * cq;
            float v0 = acc[mi][ni][0], v1 = acc[mi][ni][1];
            float v2 = acc[mi][ni][2], v3 = acc[mi][ni][3];
            if (MODE == 1) {
                if (bm >= 768) {
                    float b0 = bias[row - 768], b8 = bias[row - 768 + 8];
                    v0 = 1.f / (1.f + __expf(-(v0 + b0)));
                    v1 = 1.f / (1.f + __expf(-(v1 + b0)));
                    v2 = 1.f / (1.f + __expf(-(v2 + b8)));
                    v3 = 1.f / (1.f + __expf(-(v3 + b8)));
                } else {
                    v0 = __uint_as_float(f2tf(v0));
                    v1 = __uint_as_float(f2tf(v1));
                    v2 = __uint_as_float(f2tf(v2));
                    v3 = __uint_as_float(f2tf(v3));
                }
            } else {
                float b0 = bias[row], b8 = bias[row + 8];
                v0 += b0; v1 += b0; v2 += b8; v3 += b8;
            }
            *(float2*)&C[(size_t)row * NCOL + col]       = make_float2(v0, v1);
            *(float2*)&C[(size_t)(row + 8) * NCOL + col] = make_float2(v2, v3);
        }
    }
}

// ---------------- flash attention (391.3µs winner, byte-identical) ----------
// block = (i-64, s, h), 128 threads (4 warps x 16 rows), smem 44KB static.
#define QA 36   // qs [i][c] stride (conflict-free ldsm A)
#define KA 72   // ks [c][j] stride (conflict-free scalar B-LDS)
#define VA 68   // vs [c][j] stride (conflict-free ldsm B)

__global__ void __launch_bounds__(128, 4) k_attn() {
    __shared__ unsigned qs[64 * QA];
    __shared__ unsigned ks[2][32 * KA];
    __shared__ unsigned vs[2][32 * VA];

    int ib = blockIdx.x, s = blockIdx.y, h = blockIdx.z;
    int ibase = ib * 64;
    int tid = threadIdx.x, lane = tid & 31, warp = tid >> 5;
    size_t colb = (size_t)s * 256;
    const unsigned* qg = (const unsigned*)g_qkvg;
    const uint4* qg4 = (const uint4*)g_qkvg;

    unsigned qs_sh = (unsigned)__cvta_generic_to_shared(qs);
    unsigned ks_sh = (unsigned)__cvta_generic_to_shared(&ks[0][0]);
    unsigned vs_sh = (unsigned)__cvta_generic_to_shared(&vs[0][0]);

    // ---- cp.async stage K/V chunk 0 ([c][j], contiguous 16B) ----
#pragma unroll
    for (int it = 0; it < 4; it++) {
        int idx = tid + it * 128;
        int c = idx >> 4, j4 = (idx & 15) << 2;
        cpa16(ks_sh + (unsigned)((c * KA + j4) << 2),
              qg + ((size_t)(256 + h * 32 + c)) * NCOL + colb + j4);
        cpa16(vs_sh + (unsigned)((c * VA + j4) << 2),
              qg + ((size_t)(512 + h * 32 + c)) * NCOL + colb + j4);
    }
    asm volatile("cp.async.commit_group;" ::: "memory");

    // ---- stage Q [64 i][32 c] transposed (once) ----
#pragma unroll
    for (int it = 0; it < 4; it++) {
        int idx = tid + it * 128;
        int c = idx >> 4, i4 = idx & 15;
        uint4 v = qg4[(((size_t)(h * 32 + c)) * NCOL + colb + ibase + i4 * 4) >> 2];
        qs[(i4 * 4 + 0) * QA + c] = v.x;
        qs[(i4 * 4 + 1) * QA + c] = v.y;
        qs[(i4 * 4 + 2) * QA + c] = v.z;
        qs[(i4 * 4 + 3) * QA + c] = v.w;
    }
    asm volatile("cp.async.wait_group 0;" ::: "memory");
    __syncthreads();

    const float scale = 0.17677669529663687f;   // 1/sqrt(32)
    const float* biasp = g_bias + (size_t)h * IJ;
    const int r = lane >> 2, cq = lane & 3;
    const int wm = warp * 16;                  // warp's 16 i-rows

    // ---- preload Q a-fragments (persistent) ----
    unsigned qa[4][4];
    ldsm_x4(qa[0][0], qa[0][1], qa[0][2], qa[0][3], lds_addr_a(qs_sh, wm, 0, QA));
    ldsm_x4(qa[1][0], qa[1][1], qa[1][2], qa[1][3], lds_addr_a(qs_sh, wm, 8, QA));
    ldsm_x4(qa[2][0], qa[2][1], qa[2][2], qa[2][3], lds_addr_a(qs_sh, wm, 16, QA));
    ldsm_x4(qa[3][0], qa[3][1], qa[3][2], qa[3][3], lds_addr_a(qs_sh, wm, 24, QA));

    float acc2[4][4];                          // O accumulator: 16 rows x 32 c
#pragma unroll
    for (int ct = 0; ct < 4; ct++)
#pragma unroll
        for (int k = 0; k < 4; k++) acc2[ct][k] = 0.f;
    float m0 = -1e30f, m1 = -1e30f, l0 = 0.f, l1 = 0.f;

    for (int ch = 0; ch < 4; ch++) {
        int jb = ch * 64;
        int buf = ch & 1;
        const unsigned* kb = &ks[buf][0];
        unsigned vb_sh = vs_sh + (unsigned)((buf * 32 * VA) << 2);

        // ---- prefetch next K/V chunk into other buffer (cp.async) ----
        if (ch < 3) {
            unsigned ko = ks_sh + (unsigned)((((buf ^ 1) * 32 * KA)) << 2);
            unsigned vo = vs_sh + (unsigned)((((buf ^ 1) * 32 * VA)) << 2);
            int jb2 = jb + 64;
#pragma unroll
            for (int it = 0; it < 4; it++) {
                int idx = tid + it * 128;
                int c = idx >> 4, j4 = (idx & 15) << 2;
                cpa16(ko + (unsigned)((c * KA + j4) << 2),
                      qg + ((size_t)(256 + h * 32 + c)) * NCOL + colb + jb2 + j4);
                cpa16(vo + (unsigned)((c * VA + j4) << 2),
                      qg + ((size_t)(512 + h * 32 + c)) * NCOL + colb + jb2 + j4);
            }
            asm volatile("cp.async.commit_group;" ::: "memory");
        }

        // ---- hoisted bias loads (overlap with QK mma) ----
        float2 bb0[8], bb8[8];
        {
            const float* bp0 = biasp + (size_t)(ibase + wm + r) * 256 + jb;
            const float* bp8 = bp0 + 8 * 256;
#pragma unroll
            for (int ni = 0; ni < 8; ni++) {
                bb0[ni] = *(const float2*)(bp0 + ni * 8 + 2 * cq);
                bb8[ni] = *(const float2*)(bp8 + ni * 8 + 2 * cq);
            }
        }

        // ---- QK: M=16(i), N=64(j), K=32(c); B via conflict-free scalar LDS --
        float acc[8][4];
#pragma unroll
        for (int ni = 0; ni < 8; ni++)
#pragma unroll
            for (int k = 0; k < 4; k++) acc[ni][k] = 0.f;
#pragma unroll
        for (int kk = 0; kk < 4; kk++) {
#pragma unroll
            for (int ni = 0; ni < 8; ni++) {
                unsigned b0 = kb[(kk * 8 + cq) * KA + ni * 8 + r];
                unsigned b1 = kb[(kk * 8 + 4 + cq) * KA + ni * 8 + r];
                mma_tf32(acc[ni], qa[kk][0], qa[kk][1], qa[kk][2], qa[kk][3], b0, b1);
            }
        }

        // ---- scale + bias (registers) ----
#pragma unroll
        for (int ni = 0; ni < 8; ni++) {
            acc[ni][0] = acc[ni][0] * scale + bb0[ni].x;
            acc[ni][1] = acc[ni][1] * scale + bb0[ni].y;
            acc[ni][2] = acc[ni][2] * scale + bb8[ni].x;
            acc[ni][3] = acc[ni][3] * scale + bb8[ni].y;
        }

        // ---- register online softmax (quad shuffles only) ----
        {
            float rmax0 = -1e30f, rmax1 = -1e30f;
#pragma unroll
            for (int ni = 0; ni < 8; ni++) {
                rmax0 = fmaxf(rmax0, fmaxf(acc[ni][0], acc[ni][1]));
                rmax1 = fmaxf(rmax1, fmaxf(acc[ni][2], acc[ni][3]));
            }
#pragma unroll
            for (int off = 1; off < 4; off <<= 1) {
                rmax0 = fmaxf(rmax0, __shfl_xor_sync(0xffffffffu, rmax0, off));
                rmax1 = fmaxf(rmax1, __shfl_xor_sync(0xffffffffu, rmax1, off));
            }
            float mn0 = fmaxf(m0, rmax0), mn1 = fmaxf(m1, rmax1);
            float al0 = __expf(m0 - mn0), al1 = __expf(m1 - mn1);
            m0 = mn0; m1 = mn1;
            float sum0 = 0.f, sum1 = 0.f;
#pragma unroll
            for (int ni = 0; ni < 8; ni++) {
                acc[ni][0] = __expf(acc[ni][0] - mn0);
                acc[ni][1] = __expf(acc[ni][1] - mn0);
                acc[ni][2] = __expf(acc[ni][2] - mn1);
                acc[ni][3] = __expf(acc[ni][3] - mn1);
                sum0 += acc[ni][0] + acc[ni][1];
                sum1 += acc[ni][2] + acc[ni][3];
            }
#pragma unroll
            for (int off = 1; off < 4; off <<= 1) {
                sum0 += __shfl_xor_sync(0xffffffffu, sum0, off);
                sum1 += __shfl_xor_sync(0xffffffffu, sum1, off);
            }
            l0 = al0 * l0 + sum0;
            l1 = al1 * l1 + sum1;
#pragma unroll
            for (int ct = 0; ct < 4; ct++) {
                acc2[ct][0] *= al0; acc2[ct][1] *= al0;
                acc2[ct][2] *= al1; acc2[ct][3] *= al1;
            }
        }

        // ---- permute C-frag -> A-frag (tf32), probs never touch smem ----
        unsigned au[8][4];
        {
            int src0 = (lane & 28) | (cq >> 1);
            int src1 = src0 + 2;
            bool odd = cq & 1;
#pragma unroll
            for (int ni = 0; ni < 8; ni++) {
                float p00 = __shfl_sync(0xffffffffu, acc[ni][0], src0);
                float p01 = __shfl_sync(0xffffffffu, acc[ni][1], src0);
                float p10 = __shfl_sync(0xffffffffu, acc[ni][0], src1);
                float p11 = __shfl_sync(0xffffffffu, acc[ni][1], src1);
                float q00 = __shfl_sync(0xffffffffu, acc[ni][2], src0);
                float q01 = __shfl_sync(0xffffffffu, acc[ni][3], src0);
                float q10 = __shfl_sync(0xffffffffu, acc[ni][2], src1);
                float q11 = __shfl_sync(0xffffffffu, acc[ni][3], src1);
                au[ni][0] = f2tf(odd ? p01 : p00);   // (r,   cq)
                au[ni][1] = f2tf(odd ? q01 : q00);   // (r+8, cq)
                au[ni][2] = f2tf(odd ? p11 : p10);   // (r,   cq+4)
                au[ni][3] = f2tf(odd ? q11 : q10);   // (r+8, cq+4)
            }
        }

        // ---- AV: M=16(i), N=32(c), K=64(j); A from registers, B ldsm ----
#pragma unroll
        for (int k16i = 0; k16i < 4; k16i++) {
#pragma unroll
            for (int ct = 0; ct < 4; ct++) {
                unsigned b[4];
                ldsm_x4(b[0], b[1], b[2], b[3],
                        lds_addr_b(vb_sh, ct * 8, k16i * 16, VA));
                mma_tf32(acc2[ct], au[2 * k16i][0], au[2 * k16i][1],
                         au[2 * k16i][2], au[2 * k16i][3], b[0], b[1]);
                mma_tf32(acc2[ct], au[2 * k16i + 1][0], au[2 * k16i + 1][1],
                         au[2 * k16i + 1][2], au[2 * k16i + 1][3], b[2], b[3]);
            }
        }

        if (ch < 3) {
            asm volatile("cp.async.wait_group 0;" ::: "memory");
            __syncthreads();
        }
    }

    // ---- epilogue: normalize, stage [c][i] into vs[0], gate + store ----
    __syncthreads();
    float* stage = (float*)&vs[0][0];
    {
        float inv0 = 1.f / l0, inv8 = 1.f / l1;
#pragma unroll
        for (int ct = 0; ct < 4; ct++) {
            int c = ct * 8 + 2 * cq;
            stage[c * VA + wm + r]           = acc2[ct][0] * inv0;
            stage[(c + 1) * VA + wm + r]     = acc2[ct][1] * inv0;
            stage[c * VA + wm + r + 8]       = acc2[ct][2] * inv8;
            stage[(c + 1) * VA + wm + r + 8] = acc2[ct][3] * inv8;
        }
    }
    __syncthreads();
    for (int e = tid; e < 2048; e += 128) {
        int c2 = e >> 6, ii = e & 63;
        size_t col = colb + ibase + ii;
        float gv = g_qkvg[((size_t)(768 + h * 32 + c2)) * NCOL + col];
        g_o[((size_t)(c2 * NH + h)) * NCOL + col] =
            __uint_as_float(f2tf(stage[c2 * VA + ii] * gv));
    }
}

// ---------------------------------------------------------------------------
extern "C" void kernel_launch(void* const* d_in, const int* in_sizes, int n_in,
                              void* d_out, int out_size) {
    const float* msa  = (const float*)d_in[0];
    const float* pair = (const float*)d_in[1];
    const float* ln1w = (const float*)d_in[2];
    const float* ln1b = (const float*)d_in[3];
    const float* ln2w = (const float*)d_in[4];
    const float* ln2b = (const float*)d_in[5];
    const float* Wq   = (const float*)d_in[6];
    const float* Wk   = (const float*)d_in[7];
    const float* Wv   = (const float*)d_in[8];
    const float* Wb   = (const float*)d_in[9];
    const float* Wg   = (const float*)d_in[10];
    const float* bg   = (const float*)d_in[11];
    const float* Wrep = (const float*)d_in[12];
    const float* brep = (const float*)d_in[13];
    float* out = (float*)d_out;

    // Opt-in to >48KB dynamic smem for the GEMMs (set on pre-capture call).
    cudaFuncAttributes attr;
    cudaFuncGetAttributes(&attr, k_gemm<1>);
    if (attr.maxDynamicSharedSizeBytes < (int)GEMM_SMEM) {
        cudaFuncSetAttribute(k_gemm<1>, cudaFuncAttributeMaxDynamicSharedMemorySize, GEMM_SMEM);
    }
    cudaFuncGetAttributes(&attr, k_gemm<0>);
    if (attr.maxDynamicSharedSizeBytes < (int)GEMM_SMEM) {
        cudaFuncSetAttribute(k_gemm<0>, cudaFuncAttributeMaxDynamicSharedMemorySize, GEMM_SMEM);
    }

    k_pre<<<512 + 1280, 256>>>(msa, pair, Wq, Wk, Wv, Wg, Wrep);
    k_ln1bias<<<8192 + 256, 256>>>(msa, ln1w, ln1b, pair, ln2w, ln2b, Wb);
    k_gemm<1><<<dim3(256, 8), 256, GEMM_SMEM>>>(bg, nullptr);
    k_attn<<<dim3(4, S_DIM, NH), 128>>>();
    k_gemm<0><<<dim3(256, 2), 256, GEMM_SMEM>>>(brep, out);
}

// round 17
// speedup vs baseline: 1.1073x; 1.0462x over previous
#include <cuda_runtime.h>
#include <math.h>

// ---------------------------------------------------------------------------
// RowWiseGatedAttention — tf32 mma.sync; R10 attention/gemm + bias-in-gemm1.
// B=1, c_m=256, s=128, i=256, H=8, c_head=32, c_z=128.
// ---------------------------------------------------------------------------

#define CM     256
#define S_DIM  128
#define I_DIM  256
#define NCOL   32768            // S_DIM * I_DIM
#define CZ     128
#define IJ     65536            // I_DIM * I_DIM
#define NH     8
#define NTOT   8388608          // CM*NCOL == CZ*IJ
#define LN_EPS 1e-5f

// ---------------- scratch (static device globals; no allocation) -----------
__device__ unsigned g_x[(size_t)CM * NCOL];        // LN1(msa), tf32 bits [c][s*i]
__device__ float    g_qkvg[(size_t)4 * CM * NCOL]; // q,k,v (tf32-rounded), g (fp32)
__device__ float    g_bias[(size_t)NH * IJ];       // pair bias [h][i*j]
__device__ float    g_o[(size_t)CM * NCOL];        // gated attn out (tf32-rounded)
__device__ unsigned g_wstack[1024 * 256];          // Wq,Wk,Wv,Wg tf32 bits
__device__ unsigned g_wrep[256 * 256];             // Wrep tf32 bits
__device__ float2   g_part[2][1024];

// ---------------- tf32 / mma / ldmatrix helpers -----------------------------
__device__ __forceinline__ unsigned f2tf(float x) {
    unsigned r; asm("cvt.rna.tf32.f32 %0, %1;" : "=r"(r) : "f"(x)); return r;
}
__device__ __forceinline__ void mma_tf32(float* c, unsigned a0, unsigned a1,
                                         unsigned a2, unsigned a3,
                                         unsigned b0, unsigned b1) {
    asm volatile(
        "mma.sync.aligned.m16n8k8.row.col.f32.tf32.tf32.f32 "
        "{%0,%1,%2,%3}, {%4,%5,%6,%7}, {%8,%9}, {%0,%1,%2,%3};"
        : "+f"(c[0]), "+f"(c[1]), "+f"(c[2]), "+f"(c[3])
        : "r"(a0), "r"(a1), "r"(a2), "r"(a3), "r"(b0), "r"(b1));
}
__device__ __forceinline__ void cpa16(unsigned saddr, const void* g) {
    asm volatile("cp.async.ca.shared.global [%0], [%1], 16;" :: "r"(saddr), "l"(g));
}
__device__ __forceinline__ void ldsm_x4(unsigned& r0, unsigned& r1,
                                        unsigned& r2, unsigned& r3, unsigned addr) {
    asm volatile("ldmatrix.sync.aligned.m8n8.x4.shared.b16 {%0,%1,%2,%3}, [%4];"
                 : "=r"(r0), "=r"(r1), "=r"(r2), "=r"(r3) : "r"(addr));
}
// A-fragment (m16 x k8) address for this lane: base over [row][stride] tf32 array
__device__ __forceinline__ unsigned lds_addr_a(unsigned base, int row0, int col, int stride) {
    int lane = threadIdx.x & 31;
    int g = lane >> 3, lr = lane & 7;
    int row = row0 + lr + ((g & 1) << 3);
    int c = col + ((g >> 1) << 2);
    return base + (unsigned)((row * stride + c) << 2);
}
// B-fragment (n8 x k16) address: array is [n][k] (row-major over k)
__device__ __forceinline__ unsigned lds_addr_b(unsigned base, int n0, int k0, int stride) {
    int lane = threadIdx.x & 31;
    int g = lane >> 3, lr = lane & 7;
    return base + (unsigned)(((n0 + lr) * stride + k0 + (g << 2)) << 2);
}

// ---------------- merged pre-pass: weight cvt + both partial reductions -----
__global__ void __launch_bounds__(256) k_pre(const float* __restrict__ msa,
                                             const float* __restrict__ pair,
                                             const float* __restrict__ Wq,
                                             const float* __restrict__ Wk,
                                             const float* __restrict__ Wv,
                                             const float* __restrict__ Wg,
                                             const float* __restrict__ Wrep) {
    int bid = blockIdx.x;
    if (bid >= 512) {                // weight conversion blocks
        int t = (bid - 512) * 256 + threadIdx.x;     // 0..327679
        if (t < 262144) {
            int sel = t >> 16, off = t & 65535;
            const float* W = (sel == 0) ? Wq : (sel == 1) ? Wk : (sel == 2) ? Wv : Wg;
            g_wstack[t] = f2tf(W[off]);
        } else {
            int off = t - 262144;
            g_wrep[off] = f2tf(Wrep[off]);
        }
        return;
    }
    int which = bid >> 8;
    const float4* s4 = (const float4*)(which ? pair : msa);
    int t = (bid & 255) * 256 + threadIdx.x;         // 0..65535
    float s = 0.f, ss = 0.f;
#pragma unroll 8
    for (int k = 0; k < 32; k++) {
        float4 v = s4[t + k * 65536];
        s  += v.x + v.y + v.z + v.w;
        ss += v.x * v.x + v.y * v.y + v.z * v.z + v.w * v.w;
    }
    __shared__ float sh[256], sh2[256];
    int tid = threadIdx.x;
    sh[tid] = s; sh2[tid] = ss;
    __syncthreads();
    for (int off = 128; off; off >>= 1) {
        if (tid < off) { sh[tid] += sh[tid + off]; sh2[tid] += sh2[tid + off]; }
        __syncthreads();
    }
    if (tid == 0) g_part[which][bid & 255] = make_float2(sh[0], sh2[0]);
}

// ---------------- per-block stats reduce (deterministic, same every block) --
__device__ __forceinline__ void block_stats(int which, float& mu_out, float& rs_out) {
    int tid = threadIdx.x, lane = tid & 31, warp = tid >> 5;
    float2 p = g_part[which][tid];
    float v0 = p.x, v1 = p.y;
#pragma unroll
    for (int off = 16; off; off >>= 1) {
        v0 += __shfl_xor_sync(0xffffffffu, v0, off);
        v1 += __shfl_xor_sync(0xffffffffu, v1, off);
    }
    __shared__ float w0[8], w1[8];
    __shared__ float s_mu, s_rs;
    if (lane == 0) { w0[warp] = v0; w1[warp] = v1; }
    __syncthreads();
    if (tid == 0) {
        float a = 0.f, b = 0.f;
#pragma unroll
        for (int k = 0; k < 8; k++) { a += w0[k]; b += w1[k]; }
        const float invN = 1.f / (float)NTOT;
        float mu = a * invN;
        float var = b * invN - mu * mu;
        s_mu = mu; s_rs = rsqrtf(var + LN_EPS);
    }
    __syncthreads();
    mu_out = s_mu; rs_out = s_rs;
}

// ---------------- LN1 apply (stats fused) ------------------------------------
__global__ void __launch_bounds__(256) k_ln1(const float* __restrict__ msa,
                                             const float* __restrict__ w,
                                             const float* __restrict__ b) {
    float mu, rs;
    block_stats(0, mu, rs);
    int t = blockIdx.x * 256 + threadIdx.x;
    float4 m = ((const float4*)msa)[t];
    float4 ww = ((const float4*)w)[t];
    float4 bb = ((const float4*)b)[t];
    uint4 o;
    o.x = f2tf((m.x - mu) * rs * ww.x + bb.x);
    o.y = f2tf((m.y - mu) * rs * ww.y + bb.y);
    o.z = f2tf((m.z - mu) * rs * ww.z + bb.z);
    o.w = f2tf((m.w - mu) * rs * ww.w + bb.w);
    ((uint4*)g_x)[t] = o;
}

// ---------------- tf32 GEMM: [M x 256] @ [256 x 32768] (R10 winner) ---------
// MODE 1 also carries the pair-bias GEMV blocks at blockIdx.y == 8: they are
// DRAM-bound and fill the tensor-bound gemm's scheduling bubbles/tail.
template<int MODE>
__global__ void __launch_bounds__(256) k_gemm(const float* __restrict__ bias,
                                              float* __restrict__ Cout,
                                              const float* __restrict__ pair,
                                              const float* __restrict__ ln2w,
                                              const float* __restrict__ ln2b,
                                              const float* __restrict__ Wb) {
    __shared__ unsigned As[2][128][20];
    __shared__ unsigned Bs[2][16][136];

    if (MODE == 1 && blockIdx.y == 8) {
        // ---- pair-bias GEMV block ----
        float mu, rs;
        block_stats(1, mu, rs);
        float* wb_s = (float*)&As[0][0][0];    // reuse gemm smem (4KB)
        int tid = threadIdx.x;
        for (int e = tid; e < NH * CZ; e += 256) wb_s[e] = Wb[e];
        __syncthreads();
        int col = blockIdx.x * 256 + tid;
        float acc[NH];
#pragma unroll
        for (int o = 0; o < NH; o++) acc[o] = 0.f;
#pragma unroll 4
        for (int c = 0; c < CZ; c++) {
            size_t idx = (size_t)c * IJ + col;
            float z = (pair[idx] - mu) * rs * ln2w[idx] + ln2b[idx];
#pragma unroll
            for (int o = 0; o < NH; o++) acc[o] += wb_s[o * CZ + c] * z;
        }
#pragma unroll
        for (int o = 0; o < NH; o++) g_bias[(size_t)o * IJ + col] = acc[o];
        return;
    }

    const unsigned* A = MODE ? g_wstack : g_wrep;
    const unsigned* B = MODE ? g_x : (const unsigned*)g_o;
    float* C = MODE ? g_qkvg : Cout;

    const int tid = threadIdx.x;
    const int lane = tid & 31, warp = tid >> 5;
    const int wm = (warp & 1) * 64, wn = (warp >> 1) * 32;
    const int bm = blockIdx.y * 128, bn = blockIdx.x * 128;

    float acc[4][4][4];
#pragma unroll
    for (int i = 0; i < 4; i++)
#pragma unroll
        for (int j = 0; j < 4; j++)
#pragma unroll
            for (int k = 0; k < 4; k++) acc[i][j][k] = 0.f;

    unsigned sAb = (unsigned)__cvta_generic_to_shared(&As[0][0][0]);
    unsigned sBb = (unsigned)__cvta_generic_to_shared(&Bs[0][0][0]);

    auto load_tiles = [&](int buf, int k0) {
#pragma unroll
        for (int i = 0; i < 2; i++) {
            int idx = tid + i * 256;
            int row = idx >> 2, c4 = (idx & 3) << 2;
            cpa16(sAb + (((buf * 128 + row) * 20 + c4) << 2),
                  A + (size_t)(bm + row) * 256 + k0 + c4);
        }
#pragma unroll
        for (int i = 0; i < 2; i++) {
            int idx = tid + i * 256;
            int kk = idx >> 5, c4 = (idx & 31) << 2;
            cpa16(sBb + (((buf * 16 + kk) * 136 + c4) << 2),
                  B + (size_t)(k0 + kk) * NCOL + bn + c4);
        }
        asm volatile("cp.async.commit_group;" ::: "memory");
    };

    load_tiles(0, 0);
    int buf = 0;
    const int r = lane >> 2, cq = lane & 3;
    for (int it = 0; it < 16; it++) {
        asm volatile("cp.async.wait_group 0;" ::: "memory");
        __syncthreads();
        if (it < 15) load_tiles(buf ^ 1, (it + 1) * 16);
        unsigned abase = sAb + (unsigned)((buf * 128 * 20) << 2);
        unsigned a[4][2][4];
#pragma unroll
        for (int mi = 0; mi < 4; mi++) {
            ldsm_x4(a[mi][0][0], a[mi][0][1], a[mi][0][2], a[mi][0][3],
                    lds_addr_a(abase, wm + mi * 16, 0, 20));
            ldsm_x4(a[mi][1][0], a[mi][1][1], a[mi][1][2], a[mi][1][3],
                    lds_addr_a(abase, wm + mi * 16, 8, 20));
        }
#pragma unroll
        for (int ks = 0; ks < 2; ks++) {
            int k8 = ks * 8;
            unsigned b[4][2];
#pragma unroll
            for (int ni = 0; ni < 4; ni++) {
                int cb = wn + ni * 8 + r;
                b[ni][0] = Bs[buf][k8 + cq][cb];
                b[ni][1] = Bs[buf][k8 + 4 + cq][cb];
            }
#pragma unroll
            for (int mi = 0; mi < 4; mi++)
#pragma unroll
                for (int ni = 0; ni < 4; ni++)
                    mma_tf32(acc[mi][ni], a[mi][ks][0], a[mi][ks][1],
                             a[mi][ks][2], a[mi][ks][3], b[ni][0], b[ni][1]);
        }
        buf ^= 1;
    }

#pragma unroll
    for (int mi = 0; mi < 4; mi++) {
        int row = bm + wm + mi * 16 + r;
#pragma unroll
        for (int ni = 0; ni < 4; ni++) {
            int col = bn + wn + ni * 8 + 2 * cq;
            float v0 = acc[mi][ni][0], v1 = acc[mi][ni][1];
            float v2 = acc[mi][ni][2], v3 = acc[mi][ni][3];
            if (MODE == 1) {
                if (bm >= 768) {
                    float b0 = bias[row - 768], b8 = bias[row - 768 + 8];
                    v0 = 1.f / (1.f + __expf(-(v0 + b0)));
                    v1 = 1.f / (1.f + __expf(-(v1 + b0)));
                    v2 = 1.f / (1.f + __expf(-(v2 + b8)));
                    v3 = 1.f / (1.f + __expf(-(v3 + b8)));
                } else {
                    v0 = __uint_as_float(f2tf(v0));
                    v1 = __uint_as_float(f2tf(v1));
                    v2 = __uint_as_float(f2tf(v2));
                    v3 = __uint_as_float(f2tf(v3));
                }
            } else {
                float b0 = bias[row], b8 = bias[row + 8];
                v0 += b0; v1 += b0; v2 += b8; v3 += b8;
            }
            *(float2*)&C[(size_t)row * NCOL + col]       = make_float2(v0, v1);
            *(float2*)&C[(size_t)(row + 8) * NCOL + col] = make_float2(v2, v3);
        }
    }
}

// ---------------- flash attention (391.3µs winner, byte-identical) ----------
// block = (i-64, s, h), 128 threads (4 warps x 16 rows), smem 44KB static.
#define QA 36   // qs [i][c] stride (conflict-free ldsm A)
#define KA 72   // ks [c][j] stride (conflict-free scalar B-LDS)
#define VA 68   // vs [c][j] stride (conflict-free ldsm B)

__global__ void __launch_bounds__(128, 4) k_attn() {
    __shared__ unsigned qs[64 * QA];
    __shared__ unsigned ks[2][32 * KA];
    __shared__ unsigned vs[2][32 * VA];

    int ib = blockIdx.x, s = blockIdx.y, h = blockIdx.z;
    int ibase = ib * 64;
    int tid = threadIdx.x, lane = tid & 31, warp = tid >> 5;
    size_t colb = (size_t)s * 256;
    const unsigned* qg = (const unsigned*)g_qkvg;
    const uint4* qg4 = (const uint4*)g_qkvg;

    unsigned qs_sh = (unsigned)__cvta_generic_to_shared(qs);
    unsigned ks_sh = (unsigned)__cvta_generic_to_shared(&ks[0][0]);
    unsigned vs_sh = (unsigned)__cvta_generic_to_shared(&vs[0][0]);

    // ---- cp.async stage K/V chunk 0 ([c][j], contiguous 16B) ----
#pragma unroll
    for (int it = 0; it < 4; it++) {
        int idx = tid + it * 128;
        int c = idx >> 4, j4 = (idx & 15) << 2;
        cpa16(ks_sh + (unsigned)((c * KA + j4) << 2),
              qg + ((size_t)(256 + h * 32 + c)) * NCOL + colb + j4);
        cpa16(vs_sh + (unsigned)((c * VA + j4) << 2),
              qg + ((size_t)(512 + h * 32 + c)) * NCOL + colb + j4);
    }
    asm volatile("cp.async.commit_group;" ::: "memory");

    // ---- stage Q [64 i][32 c] transposed (once) ----
#pragma unroll
    for (int it = 0; it < 4; it++) {
        int idx = tid + it * 128;
        int c = idx >> 4, i4 = idx & 15;
        uint4 v = qg4[(((size_t)(h * 32 + c)) * NCOL + colb + ibase + i4 * 4) >> 2];
        qs[(i4 * 4 + 0) * QA + c] = v.x;
        qs[(i4 * 4 + 1) * QA + c] = v.y;
        qs[(i4 * 4 + 2) * QA + c] = v.z;
        qs[(i4 * 4 + 3) * QA + c] = v.w;
    }
    asm volatile("cp.async.wait_group 0;" ::: "memory");
    __syncthreads();

    const float scale = 0.17677669529663687f;   // 1/sqrt(32)
    const float* biasp = g_bias + (size_t)h * IJ;
    const int r = lane >> 2, cq = lane & 3;
    const int wm = warp * 16;                  // warp's 16 i-rows

    // ---- preload Q a-fragments (persistent) ----
    unsigned qa[4][4];
    ldsm_x4(qa[0][0], qa[0][1], qa[0][2], qa[0][3], lds_addr_a(qs_sh, wm, 0, QA));
    ldsm_x4(qa[1][0], qa[1][1], qa[1][2], qa[1][3], lds_addr_a(qs_sh, wm, 8, QA));
    ldsm_x4(qa[2][0], qa[2][1], qa[2][2], qa[2][3], lds_addr_a(qs_sh, wm, 16, QA));
    ldsm_x4(qa[3][0], qa[3][1], qa[3][2], qa[3][3], lds_addr_a(qs_sh, wm, 24, QA));

    float acc2[4][4];                          // O accumulator: 16 rows x 32 c
#pragma unroll
    for (int ct = 0; ct < 4; ct++)
#pragma unroll
        for (int k = 0; k < 4; k++) acc2[ct][k] = 0.f;
    float m0 = -1e30f, m1 = -1e30f, l0 = 0.f, l1 = 0.f;

    for (int ch = 0; ch < 4; ch++) {
        int jb = ch * 64;
        int buf = ch & 1;
        const unsigned* kb = &ks[buf][0];
        unsigned vb_sh = vs_sh + (unsigned)((buf * 32 * VA) << 2);

        // ---- prefetch next K/V chunk into other buffer (cp.async) ----
        if (ch < 3) {
            unsigned ko = ks_sh + (unsigned)((((buf ^ 1) * 32 * KA)) << 2);
            unsigned vo = vs_sh + (unsigned)((((buf ^ 1) * 32 * VA)) << 2);
            int jb2 = jb + 64;
#pragma unroll
            for (int it = 0; it < 4; it++) {
                int idx = tid + it * 128;
                int c = idx >> 4, j4 = (idx & 15) << 2;
                cpa16(ko + (unsigned)((c * KA + j4) << 2),
                      qg + ((size_t)(256 + h * 32 + c)) * NCOL + colb + jb2 + j4);
                cpa16(vo + (unsigned)((c * VA + j4) << 2),
                      qg + ((size_t)(512 + h * 32 + c)) * NCOL + colb + jb2 + j4);
            }
            asm volatile("cp.async.commit_group;" ::: "memory");
        }

        // ---- hoisted bias loads (overlap with QK mma) ----
        float2 bb0[8], bb8[8];
        {
            const float* bp0 = biasp + (size_t)(ibase + wm + r) * 256 + jb;
            const float* bp8 = bp0 + 8 * 256;
#pragma unroll
            for (int ni = 0; ni < 8; ni++) {
                bb0[ni] = *(const float2*)(bp0 + ni * 8 + 2 * cq);
                bb8[ni] = *(const float2*)(bp8 + ni * 8 + 2 * cq);
            }
        }

        // ---- QK: M=16(i), N=64(j), K=32(c); B via conflict-free scalar LDS --
        float acc[8][4];
#pragma unroll
        for (int ni = 0; ni < 8; ni++)
#pragma unroll
            for (int k = 0; k < 4; k++) acc[ni][k] = 0.f;
#pragma unroll
        for (int kk = 0; kk < 4; kk++) {
#pragma unroll
            for (int ni = 0; ni < 8; ni++) {
                unsigned b0 = kb[(kk * 8 + cq) * KA + ni * 8 + r];
                unsigned b1 = kb[(kk * 8 + 4 + cq) * KA + ni * 8 + r];
                mma_tf32(acc[ni], qa[kk][0], qa[kk][1], qa[kk][2], qa[kk][3], b0, b1);
            }
        }

        // ---- scale + bias (registers) ----
#pragma unroll
        for (int ni = 0; ni < 8; ni++) {
            acc[ni][0] = acc[ni][0] * scale + bb0[ni].x;
            acc[ni][1] = acc[ni][1] * scale + bb0[ni].y;
            acc[ni][2] = acc[ni][2] * scale + bb8[ni].x;
            acc[ni][3] = acc[ni][3] * scale + bb8[ni].y;
        }

        // ---- register online softmax (quad shuffles only) ----
        {
            float rmax0 = -1e30f, rmax1 = -1e30f;
#pragma unroll
            for (int ni = 0; ni < 8; ni++) {
                rmax0 = fmaxf(rmax0, fmaxf(acc[ni][0], acc[ni][1]));
                rmax1 = fmaxf(rmax1, fmaxf(acc[ni][2], acc[ni][3]));
            }
#pragma unroll
            for (int off = 1; off < 4; off <<= 1) {
                rmax0 = fmaxf(rmax0, __shfl_xor_sync(0xffffffffu, rmax0, off));
                rmax1 = fmaxf(rmax1, __shfl_xor_sync(0xffffffffu, rmax1, off));
            }
            float mn0 = fmaxf(m0, rmax0), mn1 = fmaxf(m1, rmax1);
            float al0 = __expf(m0 - mn0), al1 = __expf(m1 - mn1);
            m0 = mn0; m1 = mn1;
            float sum0 = 0.f, sum1 = 0.f;
#pragma unroll
            for (int ni = 0; ni < 8; ni++) {
                acc[ni][0] = __expf(acc[ni][0] - mn0);
                acc[ni][1] = __expf(acc[ni][1] - mn0);
                acc[ni][2] = __expf(acc[ni][2] - mn1);
                acc[ni][3] = __expf(acc[ni][3] - mn1);
                sum0 += acc[ni][0] + acc[ni][1];
                sum1 += acc[ni][2] + acc[ni][3];
            }
#pragma unroll
            for (int off = 1; off < 4; off <<= 1) {
                sum0 += __shfl_xor_sync(0xffffffffu, sum0, off);
                sum1 += __shfl_xor_sync(0xffffffffu, sum1, off);
            }
            l0 = al0 * l0 + sum0;
            l1 = al1 * l1 + sum1;
#pragma unroll
            for (int ct = 0; ct < 4; ct++) {
                acc2[ct][0] *= al0; acc2[ct][1] *= al0;
                acc2[ct][2] *= al1; acc2[ct][3] *= al1;
            }
        }

        // ---- permute C-frag -> A-frag (tf32), probs never touch smem ----
        unsigned au[8][4];
        {
            int src0 = (lane & 28) | (cq >> 1);
            int src1 = src0 + 2;
            bool odd = cq & 1;
#pragma unroll
            for (int ni = 0; ni < 8; ni++) {
                float p00 = __shfl_sync(0xffffffffu, acc[ni][0], src0);
                float p01 = __shfl_sync(0xffffffffu, acc[ni][1], src0);
                float p10 = __shfl_sync(0xffffffffu, acc[ni][0], src1);
                float p11 = __shfl_sync(0xffffffffu, acc[ni][1], src1);
                float q00 = __shfl_sync(0xffffffffu, acc[ni][2], src0);
                float q01 = __shfl_sync(0xffffffffu, acc[ni][3], src0);
                float q10 = __shfl_sync(0xffffffffu, acc[ni][2], src1);
                float q11 = __shfl_sync(0xffffffffu, acc[ni][3], src1);
                au[ni][0] = f2tf(odd ? p01 : p00);   // (r,   cq)
                au[ni][1] = f2tf(odd ? q01 : q00);   // (r+8, cq)
                au[ni][2] = f2tf(odd ? p11 : p10);   // (r,   cq+4)
                au[ni][3] = f2tf(odd ? q11 : q10);   // (r+8, cq+4)
            }
        }

        // ---- AV: M=16(i), N=32(c), K=64(j); A from registers, B ldsm ----
#pragma unroll
        for (int k16i = 0; k16i < 4; k16i++) {
#pragma unroll
            for (int ct = 0; ct < 4; ct++) {
                unsigned b[4];
                ldsm_x4(b[0], b[1], b[2], b[3],
                        lds_addr_b(vb_sh, ct * 8, k16i * 16, VA));
                mma_tf32(acc2[ct], au[2 * k16i][0], au[2 * k16i][1],
                         au[2 * k16i][2], au[2 * k16i][3], b[0], b[1]);
                mma_tf32(acc2[ct], au[2 * k16i + 1][0], au[2 * k16i + 1][1],
                         au[2 * k16i + 1][2], au[2 * k16i + 1][3], b[2], b[3]);
            }
        }

        if (ch < 3) {
            asm volatile("cp.async.wait_group 0;" ::: "memory");
            __syncthreads();
        }
    }

    // ---- epilogue: normalize, stage [c][i] into vs[0], gate + store ----
    __syncthreads();
    float* stage = (float*)&vs[0][0];
    {
        float inv0 = 1.f / l0, inv8 = 1.f / l1;
#pragma unroll
        for (int ct = 0; ct < 4; ct++) {
            int c = ct * 8 + 2 * cq;
            stage[c * VA + wm + r]           = acc2[ct][0] * inv0;
            stage[(c + 1) * VA + wm + r]     = acc2[ct][1] * inv0;
            stage[c * VA + wm + r + 8]       = acc2[ct][2] * inv8;
            stage[(c + 1) * VA + wm + r + 8] = acc2[ct][3] * inv8;
        }
    }
    __syncthreads();
    for (int e = tid; e < 2048; e += 128) {
        int c2 = e >> 6, ii = e & 63;
        size_t col = colb + ibase + ii;
        float gv = g_qkvg[((size_t)(768 + h * 32 + c2)) * NCOL + col];
        g_o[((size_t)(c2 * NH + h)) * NCOL + col] =
            __uint_as_float(f2tf(stage[c2 * VA + ii] * gv));
    }
}

// ---------------------------------------------------------------------------
extern "C" void kernel_launch(void* const* d_in, const int* in_sizes, int n_in,
                              void* d_out, int out_size) {
    const float* msa  = (const float*)d_in[0];
    const float* pair = (const float*)d_in[1];
    const float* ln1w = (const float*)d_in[2];
    const float* ln1b = (const float*)d_in[3];
    const float* ln2w = (const float*)d_in[4];
    const float* ln2b = (const float*)d_in[5];
    const float* Wq   = (const float*)d_in[6];
    const float* Wk   = (const float*)d_in[7];
    const float* Wv   = (const float*)d_in[8];
    const float* Wb   = (const float*)d_in[9];
    const float* Wg   = (const float*)d_in[10];
    const float* bg   = (const float*)d_in[11];
    const float* Wrep = (const float*)d_in[12];
    const float* brep = (const float*)d_in[13];
    float* out = (float*)d_out;

    k_pre<<<512 + 1280, 256>>>(msa, pair, Wq, Wk, Wv, Wg, Wrep);
    k_ln1<<<8192, 256>>>(msa, ln1w, ln1b);
    k_gemm<1><<<dim3(256, 9), 256>>>(bg, nullptr, pair, ln2w, ln2b, Wb);
    k_attn<<<dim3(4, S_DIM, NH), 128>>>();
    k_gemm<0><<<dim3(256, 2), 256>>>(brep, out, nullptr, nullptr, nullptr, nullptr);
}